// round 1
// baseline (speedup 1.0000x reference)
#include <cuda_runtime.h>
#include <math.h>

#define S   8192
#define H2  1024
#define AA  2048
#define EE  768
#define NTILES 16    // AA / 128
#define NCHUNK 64    // S / 128

// ---------------- scratch (device globals; no allocation) ----------------
__device__ float g_cbpart[3 * 4 * AA];
__device__ float g_cb[3 * AA];
__device__ float g_epart[(size_t)3 * NTILES * S];
__device__ float g_efull[3 * S];
__device__ float g_m[3];
__device__ float g_Zinv[3];
__device__ float g_fused[S];
__device__ float g_outpart[NCHUNK * H2];

// ---------------- 1a: partial ctx @ W_ctx ----------------
__global__ void cb_part_kernel(const float* __restrict__ ctx0, const float* __restrict__ ctx1,
                               const float* __restrict__ ctx2,
                               const float* __restrict__ Wc0, const float* __restrict__ Wc1,
                               const float* __restrict__ Wc2)
{
    int a = blockIdx.x * 256 + threadIdx.x;   // 0..2047
    int t = blockIdx.y;                       // head
    int z = blockIdx.z;                       // e-slice (192 each)
    const float* ctx = (t == 0) ? ctx0 : (t == 1) ? ctx1 : ctx2;
    const float* W   = (t == 0) ? Wc0  : (t == 1) ? Wc1  : Wc2;
    float acc = 0.f;
    int e0 = z * 192;
#pragma unroll 8
    for (int e = 0; e < 192; e++)
        acc += ctx[e0 + e] * W[(size_t)(e0 + e) * AA + a];
    g_cbpart[(t * 4 + z) * AA + a] = acc;
}

// ---------------- 1b: cb = b_sent + b_ctx + sum(parts) ----------------
__global__ void cb_final_kernel(const float* __restrict__ bs0, const float* __restrict__ bs1,
                                const float* __restrict__ bs2,
                                const float* __restrict__ bc0, const float* __restrict__ bc1,
                                const float* __restrict__ bc2)
{
    int a = blockIdx.x * 256 + threadIdx.x;
    int t = blockIdx.y;
    const float* bs = (t == 0) ? bs0 : (t == 1) ? bs1 : bs2;
    const float* bc = (t == 0) ? bc0 : (t == 1) ? bc1 : bc2;
    float acc = bs[a] + bc[a];
#pragma unroll
    for (int z = 0; z < 4; z++) acc += g_cbpart[(t * 4 + z) * AA + a];
    g_cb[t * AA + a] = acc;
}

// ---------------- 2: fused GEMM + tanh·v reduction ----------------
// Tile 128x128x16, 256 threads, 8x8 microtiles (split 2x2 of float4 for
// conflict-free LDS). Epilogue: e_part[head][ntile][row] = sum_n tanh(u+cb)*v.
__global__ __launch_bounds__(256, 2) void gemm_e_kernel(
    const float* __restrict__ sent,
    const float* __restrict__ W0, const float* __restrict__ W1, const float* __restrict__ W2,
    const float* __restrict__ v0, const float* __restrict__ v1, const float* __restrict__ v2,
    const int* __restrict__ lenp)
{
    const int BM = 128, BN = 128, BK = 16;
    int len = *lenp; if (len > S) len = S;
    int m0 = blockIdx.y * BM;
    if (m0 >= len) return;                      // masked rows never affect output
    int head = blockIdx.x >> 4;
    int ntile = blockIdx.x & 15;
    int n0 = ntile * BN;
    const float* W  = (head == 0) ? W0 : (head == 1) ? W1 : W2;
    const float* v  = (head == 0) ? v0 : (head == 1) ? v1 : v2;
    const float* cb = g_cb + head * AA;

    __shared__ float As[2][BK][BM + 4];
    __shared__ float Bs[2][BK][BN];
    __shared__ float red[128][17];

    int tid = threadIdx.x;
    int tx = tid & 15, ty = tid >> 4;

    float acc[8][8];
#pragma unroll
    for (int i = 0; i < 8; i++)
#pragma unroll
        for (int j = 0; j < 8; j++) acc[i][j] = 0.f;

    // preload K-slab 0
    {
#pragma unroll
        for (int i = 0; i < 2; i++) {
            int f = tid * 2 + i;
            int m = f >> 2, kq = f & 3;
            float4 t4 = *(const float4*)(sent + (size_t)(m0 + m) * H2 + kq * 4);
            As[0][kq * 4 + 0][m] = t4.x; As[0][kq * 4 + 1][m] = t4.y;
            As[0][kq * 4 + 2][m] = t4.z; As[0][kq * 4 + 3][m] = t4.w;
            int k = f >> 5, nq = f & 31;
            *(float4*)&Bs[0][k][nq * 4] = *(const float4*)(W + (size_t)k * AA + n0 + nq * 4);
        }
    }
    __syncthreads();

    const int NK = H2 / BK;  // 64
    for (int kk = 0; kk < NK; kk++) {
        int cur = kk & 1, nxt = cur ^ 1;
        if (kk + 1 < NK) {
            int k0 = (kk + 1) * BK;
#pragma unroll
            for (int i = 0; i < 2; i++) {
                int f = tid * 2 + i;
                int m = f >> 2, kq = f & 3;
                float4 t4 = *(const float4*)(sent + (size_t)(m0 + m) * H2 + k0 + kq * 4);
                As[nxt][kq * 4 + 0][m] = t4.x; As[nxt][kq * 4 + 1][m] = t4.y;
                As[nxt][kq * 4 + 2][m] = t4.z; As[nxt][kq * 4 + 3][m] = t4.w;
                int k = f >> 5, nq = f & 31;
                *(float4*)&Bs[nxt][k][nq * 4] = *(const float4*)(W + (size_t)(k0 + k) * AA + n0 + nq * 4);
            }
        }
#pragma unroll
        for (int k = 0; k < BK; k++) {
            float a[8], b[8];
#pragma unroll
            for (int i = 0; i < 4; i++) {
                a[i]     = As[cur][k][ty * 4 + i];
                a[4 + i] = As[cur][k][64 + ty * 4 + i];
            }
#pragma unroll
            for (int j = 0; j < 4; j++) {
                b[j]     = Bs[cur][k][tx * 4 + j];
                b[4 + j] = Bs[cur][k][64 + tx * 4 + j];
            }
#pragma unroll
            for (int i = 0; i < 8; i++)
#pragma unroll
                for (int j = 0; j < 8; j++)
                    acc[i][j] = fmaf(a[i], b[j], acc[i][j]);
        }
        __syncthreads();
    }

    // epilogue: tanh(u + cb) * v, reduce over this block's 128 N-columns
    float vv[8], cbv[8];
#pragma unroll
    for (int j = 0; j < 8; j++) {
        int c = (j < 4) ? (tx * 4 + j) : (64 + tx * 4 + (j - 4));
        vv[j]  = v[n0 + c];
        cbv[j] = cb[n0 + c];
    }
#pragma unroll
    for (int i = 0; i < 8; i++) {
        int r = (i < 4) ? (ty * 4 + i) : (64 + ty * 4 + (i - 4));
        float s = 0.f;
#pragma unroll
        for (int j = 0; j < 8; j++)
            s += tanhf(acc[i][j] + cbv[j]) * vv[j];
        red[r][tx] = s;
    }
    __syncthreads();
    if (tid < 128) {
        float s = 0.f;
#pragma unroll
        for (int x = 0; x < 16; x++) s += red[tid][x];
        g_epart[(size_t)(head * NTILES + ntile) * S + m0 + tid] = s;
    }
}

// ---------------- 3: finalize e, masked softmax stats (one block per head) ----
__global__ void softmax_stats_kernel(const float* __restrict__ bv0, const float* __restrict__ bv1,
                                     const float* __restrict__ bv2, const int* __restrict__ lenp)
{
    __shared__ float sm[1024];
    int t = blockIdx.x, tid = threadIdx.x;
    int len = *lenp; if (len > S) len = S;
    if (len <= 0) { if (tid == 0) { g_m[t] = 0.f; g_Zinv[t] = 0.f; } return; }
    float bv = (t == 0) ? *bv0 : (t == 1) ? *bv1 : *bv2;
    const float NEGINF = __int_as_float(0xff800000);
    float vals[8];
    float mx = NEGINF;
#pragma unroll
    for (int i = 0; i < 8; i++) {
        int s = tid + i * 1024;
        float val = NEGINF;
        if (s < len) {
            val = bv;
#pragma unroll
            for (int nt = 0; nt < NTILES; nt++)
                val += g_epart[(size_t)(t * NTILES + nt) * S + s];
        }
        vals[i] = val;
        g_efull[t * S + s] = val;
        mx = fmaxf(mx, val);
    }
    sm[tid] = mx; __syncthreads();
    for (int off = 512; off > 0; off >>= 1) {
        if (tid < off) sm[tid] = fmaxf(sm[tid], sm[tid + off]);
        __syncthreads();
    }
    float m = sm[0]; __syncthreads();
    float z = 0.f;
#pragma unroll
    for (int i = 0; i < 8; i++) z += expf(vals[i] - m);  // exp(-inf) = 0
    sm[tid] = z; __syncthreads();
    for (int off = 512; off > 0; off >>= 1) {
        if (tid < off) sm[tid] += sm[tid + off];
        __syncthreads();
    }
    if (tid == 0) { g_m[t] = m; g_Zinv[t] = 1.f / sm[0]; }
}

// ---------------- 4: fused = mean of 3 softmax weights ----------------
__global__ void fused_kernel(const int* __restrict__ lenp)
{
    int s = blockIdx.x * 256 + threadIdx.x;
    int len = *lenp; if (len > S) len = S;
    float f = 0.f;
    if (s < len) {
#pragma unroll
        for (int t = 0; t < 3; t++)
            f += expf(g_efull[t * S + s] - g_m[t]) * g_Zinv[t];
        f *= (1.f / 3.f);
    }
    g_fused[s] = f;
}

// ---------------- 5: out_part[c][h] = sum over 128-row chunk ----------------
__global__ void outpart_kernel(const float* __restrict__ sent, const int* __restrict__ lenp)
{
    int c = blockIdx.x, h = threadIdx.x;     // blockDim = 1024
    int len = *lenp; if (len > S) len = S;
    float acc = 0.f;
    int s0 = c * 128;
    int send = min(s0 + 128, len);
    for (int s = s0; s < send; s++)
        acc += g_fused[s] * sent[(size_t)s * H2 + h];
    g_outpart[c * H2 + h] = acc;
}

// ---------------- 6: final reduce ----------------
__global__ void final_kernel(float* __restrict__ out)
{
    int h = blockIdx.x * 256 + threadIdx.x;
    float acc = 0.f;
#pragma unroll
    for (int c = 0; c < NCHUNK; c++) acc += g_outpart[c * H2 + h];
    out[h] = acc;
}

// ---------------- launch ----------------
extern "C" void kernel_launch(void* const* d_in, const int* in_sizes, int n_in,
                              void* d_out, int out_size)
{
    const float* sent = (const float*)d_in[0];
    const int*   len  = (const int*)d_in[1];
    const float* pos  = (const float*)d_in[2];
    const float* card = (const float*)d_in[3];
    const float* hdl  = (const float*)d_in[4];

    const float* Ws_p = (const float*)d_in[5];
    const float* bs_p = (const float*)d_in[6];
    const float* Wc_p = (const float*)d_in[7];
    const float* bc_p = (const float*)d_in[8];
    const float* v_p  = (const float*)d_in[9];
    const float* bv_p = (const float*)d_in[10];

    const float* Ws_c = (const float*)d_in[11];
    const float* bs_c = (const float*)d_in[12];
    const float* Wc_c = (const float*)d_in[13];
    const float* bc_c = (const float*)d_in[14];
    const float* v_c  = (const float*)d_in[15];
    const float* bv_c = (const float*)d_in[16];

    const float* Ws_h = (const float*)d_in[17];
    const float* bs_h = (const float*)d_in[18];
    const float* Wc_h = (const float*)d_in[19];
    const float* bc_h = (const float*)d_in[20];
    const float* v_h  = (const float*)d_in[21];
    const float* bv_h = (const float*)d_in[22];

    float* out = (float*)d_out;

    cb_part_kernel<<<dim3(AA / 256, 3, 4), 256>>>(pos, card, hdl, Wc_p, Wc_c, Wc_h);
    cb_final_kernel<<<dim3(AA / 256, 3), 256>>>(bs_p, bs_c, bs_h, bc_p, bc_c, bc_h);
    gemm_e_kernel<<<dim3(3 * NTILES, S / 128), 256>>>(sent, Ws_p, Ws_c, Ws_h,
                                                      v_p, v_c, v_h, len);
    softmax_stats_kernel<<<3, 1024>>>(bv_p, bv_c, bv_h, len);
    fused_kernel<<<S / 256, 256>>>(len);
    outpart_kernel<<<NCHUNK, 1024>>>(sent, len);
    final_kernel<<<H2 / 256, 256>>>(out);
}

// round 3
// speedup vs baseline: 2.8425x; 2.8425x over previous
#include <cuda_runtime.h>
#include <cuda_bf16.h>
#include <math.h>
#include <stdint.h>

#define S   8192
#define H2  1024
#define AA  2048
#define NT  8        // N-tiles of 256 per head
#define KTC 96       // K'-chunks of 32 (K' = 3*1024 = 3072)
#define MT  64       // M-tiles of 128
#define NCHUNK 64

// A tiles: [mt][96][128 rows][32 halves] (8KB per chunk, SW64 rows of 64B)
// B tiles: [head*8+nt][96][4 sub][32 k][64 n halves] (16KB per chunk, SW128)
__device__ char  g_Abf[(size_t)MT * KTC * 8192];            // 48 MB
__device__ char  g_Bbf[(size_t)3 * NT * KTC * 16384];       // 36 MB
__device__ float g_cbpart[3 * 4 * AA];
__device__ float g_cb[3 * AA];
__device__ float g_epart[(size_t)3 * NT * S];
__device__ float g_efull[3 * S];
__device__ float g_m[3];
__device__ float g_Zinv[3];
__device__ float g_fused[S];
__device__ float g_outpart[NCHUNK * H2];

// ---------------- helpers ----------------
__device__ __forceinline__ uint32_t smem_u32(const void* p) {
    uint32_t a;
    asm("{ .reg .u64 t; cvta.to.shared.u64 t, %1; cvt.u32.u64 %0, t; }" : "=r"(a) : "l"(p));
    return a;
}
__device__ __forceinline__ uint32_t sw64(uint32_t x)  { return x ^ ((x >> 3) & 0x30); }
__device__ __forceinline__ uint32_t sw128(uint32_t x) { return x ^ ((x >> 3) & 0x70); }

__device__ __forceinline__ void cp16(uint32_t saddr, const void* gaddr) {
    asm volatile("cp.async.cg.shared.global [%0], [%1], 16;" :: "r"(saddr), "l"(gaddr));
}
__device__ __forceinline__ void cp_commit() { asm volatile("cp.async.commit_group;"); }
__device__ __forceinline__ void cp_wait1()  { asm volatile("cp.async.wait_group 1;"); }
__device__ __forceinline__ void cp_wait0()  { asm volatile("cp.async.wait_group 0;"); }

__device__ __forceinline__ void ldsm4(uint32_t* r, uint32_t addr) {
    asm volatile("ldmatrix.sync.aligned.m8n8.x4.shared.b16 {%0,%1,%2,%3}, [%4];"
                 : "=r"(r[0]), "=r"(r[1]), "=r"(r[2]), "=r"(r[3]) : "r"(addr));
}
__device__ __forceinline__ void ldsm4t(uint32_t* r, uint32_t addr) {
    asm volatile("ldmatrix.sync.aligned.m8n8.x4.trans.shared.b16 {%0,%1,%2,%3}, [%4];"
                 : "=r"(r[0]), "=r"(r[1]), "=r"(r[2]), "=r"(r[3]) : "r"(addr));
}
__device__ __forceinline__ void mma16816(float* d, const uint32_t* a, uint32_t b0, uint32_t b1) {
    asm volatile(
        "mma.sync.aligned.m16n8k16.row.col.f32.bf16.bf16.f32 "
        "{%0,%1,%2,%3}, {%4,%5,%6,%7}, {%8,%9}, {%0,%1,%2,%3};"
        : "+f"(d[0]), "+f"(d[1]), "+f"(d[2]), "+f"(d[3])
        : "r"(a[0]), "r"(a[1]), "r"(a[2]), "r"(a[3]), "r"(b0), "r"(b1));
}
__device__ __forceinline__ float tanha(float x) {
    float y;
    asm("tanh.approx.f32 %0, %1;" : "=f"(y) : "f"(x));
    return y;
}

// ---------------- conv A: fp32 sentence -> bf16 hi/lo/hi swizzled tiles ------
__global__ void convA_kernel(const float* __restrict__ sent, const int* __restrict__ lenp)
{
    int len = *lenp; if (len > S) len = S;
    int mlim = (len + 127) & ~127;
    int idx = blockIdx.x * 256 + threadIdx.x;
    int m = idx >> 10;
    if (m >= mlim) return;
    int k = idx & 1023;
    float x = sent[idx];
    __nv_bfloat16 hi = __float2bfloat16(x);
    __nv_bfloat16 lo = __float2bfloat16(x - __bfloat162float(hi));
    int mt = m >> 7, r = m & 127, kc = k >> 5, c = k & 31;
    uint32_t off = sw64((uint32_t)(r * 64 + c * 2));
    char* base = g_Abf + (size_t)mt * KTC * 8192;
    *(__nv_bfloat16*)(base + (size_t)kc * 8192 + off)        = hi;
    *(__nv_bfloat16*)(base + (size_t)(32 + kc) * 8192 + off) = lo;
    *(__nv_bfloat16*)(base + (size_t)(64 + kc) * 8192 + off) = hi;
}

// ---------------- conv B: W[k][n] -> bf16 hi/hi/lo swizzled [k][n] tiles -----
__global__ void convB_kernel(const float* __restrict__ W0, const float* __restrict__ W1,
                             const float* __restrict__ W2)
{
    int idx = blockIdx.x * 256 + threadIdx.x;
    int head = idx >> 21;
    int rem = idx & ((1 << 21) - 1);
    int k = rem >> 11, n = rem & 2047;
    const float* W = (head == 0) ? W0 : (head == 1) ? W1 : W2;
    float x = W[rem];
    __nv_bfloat16 hi = __float2bfloat16(x);
    __nv_bfloat16 lo = __float2bfloat16(x - __bfloat162float(hi));
    int nt = n >> 8, nloc = n & 255, sub = nloc >> 6, nc = nloc & 63;
    int kc = k >> 5, kr = k & 31;
    uint32_t off = (uint32_t)(sub * 4096) + sw128((uint32_t)(kr * 128 + nc * 2));
    char* base = g_Bbf + (size_t)(head * NT + nt) * KTC * 16384;
    *(__nv_bfloat16*)(base + (size_t)kc * 16384 + off)        = hi;
    *(__nv_bfloat16*)(base + (size_t)(32 + kc) * 16384 + off) = hi;
    *(__nv_bfloat16*)(base + (size_t)(64 + kc) * 16384 + off) = lo;
}

// ---------------- context bias ----------------
__global__ void cb_part_kernel(const float* __restrict__ ctx0, const float* __restrict__ ctx1,
                               const float* __restrict__ ctx2,
                               const float* __restrict__ Wc0, const float* __restrict__ Wc1,
                               const float* __restrict__ Wc2)
{
    int a = blockIdx.x * 256 + threadIdx.x;
    int t = blockIdx.y;
    int z = blockIdx.z;
    const float* ctx = (t == 0) ? ctx0 : (t == 1) ? ctx1 : ctx2;
    const float* W   = (t == 0) ? Wc0  : (t == 1) ? Wc1  : Wc2;
    float acc = 0.f;
    int e0 = z * 192;
#pragma unroll 8
    for (int e = 0; e < 192; e++)
        acc += ctx[e0 + e] * W[(size_t)(e0 + e) * AA + a];
    g_cbpart[(t * 4 + z) * AA + a] = acc;
}

__global__ void cb_final_kernel(const float* __restrict__ bs0, const float* __restrict__ bs1,
                                const float* __restrict__ bs2,
                                const float* __restrict__ bc0, const float* __restrict__ bc1,
                                const float* __restrict__ bc2)
{
    int a = blockIdx.x * 256 + threadIdx.x;
    int t = blockIdx.y;
    const float* bs = (t == 0) ? bs0 : (t == 1) ? bs1 : bs2;
    const float* bc = (t == 0) ? bc0 : (t == 1) ? bc1 : bc2;
    float acc = bs[a] + bc[a];
#pragma unroll
    for (int z = 0; z < 4; z++) acc += g_cbpart[(t * 4 + z) * AA + a];
    g_cb[t * AA + a] = acc;
}

// ---------------- GEMM via mma.sync bf16 + tanh.v epilogue ----------------
// CTA 128x256, 8 warps (2x4), warp tile 64x64, BK=32, 2-stage cp.async.
__global__ __launch_bounds__(256) void gemm_e_mma(
    const float* __restrict__ v0, const float* __restrict__ v1, const float* __restrict__ v2,
    const int* __restrict__ lenp)
{
    __shared__ char smem[49152];   // 2 stages x (A 8KB + B 16KB)
    int len = *lenp; if (len > S) len = S;
    int mt_blk = blockIdx.y;
    int m0 = mt_blk << 7;
    if (m0 >= len) return;
    int head = blockIdx.x >> 3, nt_blk = blockIdx.x & 7;

    int tid = threadIdx.x, l = tid & 31, wid = tid >> 5;
    int warp_m = wid >> 2, warp_n = wid & 3;
    uint32_t sb = smem_u32(smem);

    const char* gA = g_Abf + (size_t)mt_blk * KTC * 8192;
    const char* gB = g_Bbf + (size_t)(head * NT + nt_blk) * KTC * 16384;

    float acc[4][8][4];
#pragma unroll
    for (int i = 0; i < 4; i++)
#pragma unroll
        for (int j = 0; j < 8; j++)
#pragma unroll
            for (int q = 0; q < 4; q++) acc[i][j][q] = 0.f;

    // stage fill: A 8KB (2x16B/thread) + B 16KB (4x16B/thread)
    auto issue = [&](int i) {
        uint32_t sA = sb + (uint32_t)(i & 1) * 24576;
        uint32_t sB = sA + 8192;
        const char* srcA = gA + (size_t)i * 8192;
        const char* srcB = gB + (size_t)i * 16384;
#pragma unroll
        for (int t = 0; t < 2; t++)
            cp16(sA + (uint32_t)(tid + t * 256) * 16, srcA + (size_t)(tid + t * 256) * 16);
#pragma unroll
        for (int t = 0; t < 4; t++)
            cp16(sB + (uint32_t)(tid + t * 256) * 16, srcB + (size_t)(tid + t * 256) * 16);
        cp_commit();
    };

    issue(0);
    for (int i = 0; i < KTC; i++) {
        if (i + 1 < KTC) { issue(i + 1); cp_wait1(); }
        else             { cp_wait0(); }
        __syncthreads();

        uint32_t aBase = sb + (uint32_t)(i & 1) * 24576;
        uint32_t bBase = aBase + 8192 + (uint32_t)warp_n * 4096;
#pragma unroll
        for (int ks = 0; ks < 2; ks++) {
            uint32_t af[4][4];
#pragma unroll
            for (int mt = 0; mt < 4; mt++) {
                uint32_t addr = aBase + sw64((uint32_t)((warp_m * 64 + mt * 16 + (l & 15)) * 64
                                                        + ks * 32 + (l >> 4) * 16));
                ldsm4(af[mt], addr);
            }
            uint32_t bf[4][4];
#pragma unroll
            for (int g = 0; g < 4; g++) {
                uint32_t addr = bBase + sw128((uint32_t)((ks * 16 + (l & 15)) * 128
                                                         + (g * 16 + (l >> 4) * 8) * 2));
                ldsm4t(bf[g], addr);
            }
#pragma unroll
            for (int mt = 0; mt < 4; mt++)
#pragma unroll
                for (int g = 0; g < 4; g++) {
                    mma16816(acc[mt][2 * g],     af[mt], bf[g][0], bf[g][1]);
                    mma16816(acc[mt][2 * g + 1], af[mt], bf[g][2], bf[g][3]);
                }
        }
        __syncthreads();
    }

    // epilogue: e_row = sum_n tanh(u + cb[n]) * v[n]
    const float* v  = (head == 0) ? v0 : (head == 1) ? v1 : v2;
    const float* cb = g_cb + head * AA;
    int nbase = nt_blk * 256 + warp_n * 64;

    float rs[8];
#pragma unroll
    for (int i = 0; i < 8; i++) rs[i] = 0.f;
#pragma unroll
    for (int j = 0; j < 8; j++) {
        int c = nbase + j * 8 + (l & 3) * 2;
        float cb0 = __ldg(cb + c), cb1 = __ldg(cb + c + 1);
        float vv0 = __ldg(v + c),  vv1 = __ldg(v + c + 1);
#pragma unroll
        for (int mt = 0; mt < 4; mt++) {
            const float* a = acc[mt][j];
            rs[mt * 2 + 0] += tanha(a[0] + cb0) * vv0 + tanha(a[1] + cb1) * vv1;
            rs[mt * 2 + 1] += tanha(a[2] + cb0) * vv0 + tanha(a[3] + cb1) * vv1;
        }
    }
#pragma unroll
    for (int i = 0; i < 8; i++) {
        rs[i] += __shfl_xor_sync(0xffffffffu, rs[i], 1);
        rs[i] += __shfl_xor_sync(0xffffffffu, rs[i], 2);
    }
    float* red = (float*)smem;   // aliased over stage buffers (mainloop done)
    if ((l & 3) == 0) {
#pragma unroll
        for (int mt = 0; mt < 4; mt++)
#pragma unroll
            for (int h = 0; h < 2; h++) {
                int row = warp_m * 64 + mt * 16 + h * 8 + (l >> 2);
                red[row * 4 + warp_n] = rs[mt * 2 + h];
            }
    }
    __syncthreads();
    if (tid < 128) {
        float e = red[tid * 4] + red[tid * 4 + 1] + red[tid * 4 + 2] + red[tid * 4 + 3];
        g_epart[(size_t)(head * NT + nt_blk) * S + m0 + tid] = e;
    }
}

// ---------------- masked softmax stats ----------------
__global__ void softmax_stats_kernel(const float* __restrict__ bv0, const float* __restrict__ bv1,
                                     const float* __restrict__ bv2, const int* __restrict__ lenp)
{
    __shared__ float sm[1024];
    int t = blockIdx.x, tid = threadIdx.x;
    int len = *lenp; if (len > S) len = S;
    if (len <= 0) { if (tid == 0) { g_m[t] = 0.f; g_Zinv[t] = 0.f; } return; }
    float bv = (t == 0) ? *bv0 : (t == 1) ? *bv1 : *bv2;
    const float NEGINF = __int_as_float(0xff800000);
    float vals[8];
    float mx = NEGINF;
#pragma unroll
    for (int i = 0; i < 8; i++) {
        int s = tid + i * 1024;
        float val = NEGINF;
        if (s < len) {
            val = bv;
#pragma unroll
            for (int ntt = 0; ntt < NT; ntt++)
                val += g_epart[(size_t)(t * NT + ntt) * S + s];
        }
        vals[i] = val;
        g_efull[t * S + s] = val;
        mx = fmaxf(mx, val);
    }
    sm[tid] = mx; __syncthreads();
    for (int off = 512; off > 0; off >>= 1) {
        if (tid < off) sm[tid] = fmaxf(sm[tid], sm[tid + off]);
        __syncthreads();
    }
    float m = sm[0]; __syncthreads();
    float z = 0.f;
#pragma unroll
    for (int i = 0; i < 8; i++) z += expf(vals[i] - m);
    sm[tid] = z; __syncthreads();
    for (int off = 512; off > 0; off >>= 1) {
        if (tid < off) sm[tid] += sm[tid + off];
        __syncthreads();
    }
    if (tid == 0) { g_m[t] = m; g_Zinv[t] = 1.f / sm[0]; }
}

// ---------------- fused weights ----------------
__global__ void fused_kernel(const int* __restrict__ lenp)
{
    int s = blockIdx.x * 256 + threadIdx.x;
    int len = *lenp; if (len > S) len = S;
    float f = 0.f;
    if (s < len) {
#pragma unroll
        for (int t = 0; t < 3; t++)
            f += expf(g_efull[t * S + s] - g_m[t]) * g_Zinv[t];
        f *= (1.f / 3.f);
    }
    g_fused[s] = f;
}

// ---------------- weighted sum over sentence ----------------
__global__ void outpart_kernel(const float* __restrict__ sent, const int* __restrict__ lenp)
{
    int c = blockIdx.x, h = threadIdx.x;
    int len = *lenp; if (len > S) len = S;
    float acc = 0.f;
    int s0 = c * 128;
    int send = min(s0 + 128, len);
    for (int s = s0; s < send; s++)
        acc += g_fused[s] * sent[(size_t)s * H2 + h];
    g_outpart[c * H2 + h] = acc;
}

__global__ void final_kernel(float* __restrict__ out)
{
    int h = blockIdx.x * 256 + threadIdx.x;
    float acc = 0.f;
#pragma unroll
    for (int c = 0; c < NCHUNK; c++) acc += g_outpart[c * H2 + h];
    out[h] = acc;
}

// ---------------- launch ----------------
extern "C" void kernel_launch(void* const* d_in, const int* in_sizes, int n_in,
                              void* d_out, int out_size)
{
    const float* sent = (const float*)d_in[0];
    const int*   len  = (const int*)d_in[1];
    const float* pos  = (const float*)d_in[2];
    const float* card = (const float*)d_in[3];
    const float* hdl  = (const float*)d_in[4];

    const float* Ws_p = (const float*)d_in[5];
    const float* bs_p = (const float*)d_in[6];
    const float* Wc_p = (const float*)d_in[7];
    const float* bc_p = (const float*)d_in[8];
    const float* v_p  = (const float*)d_in[9];
    const float* bv_p = (const float*)d_in[10];

    const float* Ws_c = (const float*)d_in[11];
    const float* bs_c = (const float*)d_in[12];
    const float* Wc_c = (const float*)d_in[13];
    const float* bc_c = (const float*)d_in[14];
    const float* v_c  = (const float*)d_in[15];
    const float* bv_c = (const float*)d_in[16];

    const float* Ws_h = (const float*)d_in[17];
    const float* bs_h = (const float*)d_in[18];
    const float* Wc_h = (const float*)d_in[19];
    const float* bc_h = (const float*)d_in[20];
    const float* v_h  = (const float*)d_in[21];
    const float* bv_h = (const float*)d_in[22];

    float* out = (float*)d_out;

    convA_kernel<<<(S * H2) / 256, 256>>>(sent, len);
    convB_kernel<<<(3 * H2 * AA) / 256, 256>>>(Ws_p, Ws_c, Ws_h);
    cb_part_kernel<<<dim3(AA / 256, 3, 4), 256>>>(pos, card, hdl, Wc_p, Wc_c, Wc_h);
    cb_final_kernel<<<dim3(AA / 256, 3), 256>>>(bs_p, bs_c, bs_h, bc_p, bc_c, bc_h);
    gemm_e_mma<<<dim3(3 * NT, MT), 256>>>(v_p, v_c, v_h, len);
    softmax_stats_kernel<<<3, 1024>>>(bv_p, bv_c, bv_h, len);
    fused_kernel<<<S / 256, 256>>>(len);
    outpart_kernel<<<NCHUNK, 1024>>>(sent, len);
    final_kernel<<<H2 / 256, 256>>>(out);
}